// round 1
// baseline (speedup 1.0000x reference)
#include <cuda_runtime.h>
#include <cuda_bf16.h>
#include <math.h>

// Problem constants (fixed shapes)
#define NN 8192
#define NB 32
#define NG 256      // nodes per graph
#define NE 65536
#define DK 512
#define HH 32
#define VB 2048
#define VF 512
#define EPS 1e-5f

// ---------------- device scratch (no allocations allowed) ----------------
__device__ float g_c[NN], g_d[NN];          // attention-derived scalars per node
__device__ float g_sB[NN], g_sF[NN];        // per-node scalar message payloads
__device__ float g_rnB[NN], g_rnF[NN];      // reciprocal norms of visual vectors
__device__ float g_P0[DK], g_P1[DK];        // centered Wv rows
__device__ float g_M1[DK], g_M2[DK], g_M3[DK]; // folded mlp_W projections
__device__ float g_cst[12];
// g_cst: 0..3 = g00,g01,g10,g11 ; 4..6 = s00,s01,s11 ; 7 = out_const ; 8 = bias2 ; 9 = bias3

// ---------------- helpers ----------------
__device__ __forceinline__ float blockReduceSum(float v, float* red) {
    int t = threadIdx.x;
    red[t] = v;
    __syncthreads();
    for (int s = blockDim.x >> 1; s > 0; s >>= 1) {
        if (t < s) red[t] += red[t + s];
        __syncthreads();
    }
    float r = red[0];
    __syncthreads();
    return r;
}

__device__ __forceinline__ float warpSum(float v) {
    #pragma unroll
    for (int o = 16; o; o >>= 1) v += __shfl_xor_sync(0xFFFFFFFFu, v, o);
    return v;
}

// ---------------- K0: one-block precompute of all small constants ----------------
__global__ void precompute_kernel(
    const float* __restrict__ Wq, const float* __restrict__ Wk, const float* __restrict__ Wv,
    const float* __restrict__ mlp_W, const float* __restrict__ mlp_b,
    const float* __restrict__ np_W, const float* __restrict__ np_b,
    const float* __restrict__ body_W, const float* __restrict__ body_b,
    const float* __restrict__ face_W, const float* __restrict__ face_b,
    const float* __restrict__ pb_W, const float* __restrict__ pb_b,
    const float* __restrict__ pf_W, const float* __restrict__ pf_b)
{
    __shared__ float red[512];
    __shared__ float sh_u2[HH], sh_u3[HH];
    __shared__ float sh_res[12];
    int t = threadIdx.x;   // 512 threads

    // u2 = body_W @ pb_W ; u3 = face_W @ pf_W  (each [32])
    if (t < HH) {
        float a2 = 0.f, a3 = 0.f;
        #pragma unroll
        for (int j = 0; j < HH; ++j) {
            a2 += body_W[t * HH + j] * pb_W[j];
            a3 += face_W[t * HH + j] * pf_W[j];
        }
        sh_u2[t] = a2;
        sh_u3[t] = a3;
    }
    __syncthreads();

    float wq0 = Wq[t], wq1 = Wq[DK + t];
    float wk0 = Wk[t], wk1 = Wk[DK + t];
    float wv0 = Wv[t], wv1 = Wv[DK + t];

    float g00 = blockReduceSum(wq0 * wk0, red);
    float g01 = blockReduceSum(wq0 * wk1, red);
    float g10 = blockReduceSum(wq1 * wk0, red);
    float g11 = blockReduceSum(wq1 * wk1, red);
    float sum0 = blockReduceSum(wv0, red);
    float sum1 = blockReduceSum(wv1, red);
    float sq00 = blockReduceSum(wv0 * wv0, red);
    float sq01 = blockReduceSum(wv0 * wv1, red);
    float sq11 = blockReduceSum(wv1 * wv1, red);
    float bu1 = blockReduceSum(t < HH ? mlp_b[t] * np_W[t] : 0.f, red);
    float bu2 = blockReduceSum(t < HH ? mlp_b[t] * sh_u2[t] : 0.f, red);
    float bu3 = blockReduceSum(t < HH ? mlp_b[t] * sh_u3[t] : 0.f, red);
    float bvB = blockReduceSum(t < HH ? body_b[t] * pb_W[t] : 0.f, red);
    float bvF = blockReduceSum(t < HH ? face_b[t] * pf_W[t] : 0.f, red);

    if (t == 0) {
        float m0 = sum0 / (float)DK, m1 = sum1 / (float)DK;
        sh_res[0] = g00; sh_res[1] = g01; sh_res[2] = g10; sh_res[3] = g11;
        sh_res[4] = sq00 / (float)DK - m0 * m0;   // s00
        sh_res[5] = sq01 / (float)DK - m0 * m1;   // s01
        sh_res[6] = sq11 / (float)DK - m1 * m1;   // s11
        sh_res[7] = bu1 + np_b[0] + pb_b[0] + pf_b[0]; // out_const
        sh_res[8] = bu2 + bvB;                          // bias2
        sh_res[9] = bu3 + bvF;                          // bias3
        sh_res[10] = m0;
        sh_res[11] = m1;
    }
    __syncthreads();

    if (t < 12) g_cst[t] = sh_res[t];

    float m0 = sh_res[10], m1 = sh_res[11];
    g_P0[t] = wv0 - m0;
    g_P1[t] = wv1 - m1;

    float a1 = 0.f, a2 = 0.f, a3 = 0.f;
    #pragma unroll
    for (int l = 0; l < HH; ++l) {
        float w = mlp_W[t * HH + l];
        a1 += w * np_W[l];
        a2 += w * sh_u2[l];
        a3 += w * sh_u3[l];
    }
    g_M1[t] = a1;
    g_M2[t] = a2;
    g_M3[t] = a3;
}

// ---------------- K_norm: reciprocal norms of visual rows (warp per node) ----------------
template<int D4>
__global__ void norm_kernel(const float* __restrict__ vis, float* __restrict__ rn) {
    int warp = (blockIdx.x * blockDim.x + threadIdx.x) >> 5;
    int lane = threadIdx.x & 31;
    if (warp >= NN) return;
    const float4* v = reinterpret_cast<const float4*>(vis) + (size_t)warp * D4;
    float acc = 0.f;
    #pragma unroll 4
    for (int k = lane; k < D4; k += 32) {
        float4 p = v[k];
        acc += p.x * p.x + p.y * p.y + p.z * p.z + p.w * p.w;
    }
    acc = warpSum(acc);
    if (lane == 0) rn[warp] = rsqrtf(acc + 1e-8f);
}

// ---------------- K_attn: per-graph rank-2 attention -> (c,d) per node ----------------
__global__ void attn_kernel(const float* __restrict__ x) {
    __shared__ float sa[NG], sb[NG];
    int g = blockIdx.x;
    int t = threadIdx.x;      // 256 threads
    int node = g * NG + t;
    sa[t] = x[2 * node];
    sb[t] = x[2 * node + 1];
    __syncthreads();

    float g00 = g_cst[0], g01 = g_cst[1], g10 = g_cst[2], g11 = g_cst[3];
    const float inv = 0.04419417382415922f; // 1/sqrt(512)
    int warp = t >> 5, lane = t & 31;

    for (int i = warp; i < NG; i += 8) {
        float ai = sa[i], bi = sb[i];
        float alpha = (ai * g00 + bi * g10) * inv;
        float beta  = (ai * g01 + bi * g11) * inv;
        float m = -1e30f;
        #pragma unroll
        for (int j = lane; j < NG; j += 32)
            m = fmaxf(m, alpha * sa[j] + beta * sb[j]);
        #pragma unroll
        for (int o = 16; o; o >>= 1) m = fmaxf(m, __shfl_xor_sync(0xFFFFFFFFu, m, o));
        float s = 0.f, sA = 0.f, sBv = 0.f;
        #pragma unroll
        for (int j = lane; j < NG; j += 32) {
            float e = __expf(alpha * sa[j] + beta * sb[j] - m);
            s += e; sA += e * sa[j]; sBv += e * sb[j];
        }
        s = warpSum(s); sA = warpSum(sA); sBv = warpSum(sBv);
        if (lane == 0) {
            g_c[g * NG + i] = sA / s;
            g_d[g * NG + i] = sBv / s;
        }
    }
}

// ---------------- K_node: LN + PReLU + folded projections (warp per node) ----------------
__global__ void node_kernel(const float* __restrict__ ln_g, const float* __restrict__ ln_b,
                            const float* __restrict__ prelu_a, float* __restrict__ out) {
    int warp = (blockIdx.x * blockDim.x + threadIdx.x) >> 5;
    int lane = threadIdx.x & 31;
    if (warp >= NN) return;
    float c = g_c[warp], d = g_d[warp];
    float s00 = g_cst[4], s01 = g_cst[5], s11 = g_cst[6];
    float var = c * c * s00 + 2.f * c * d * s01 + d * d * s11;
    float rstd = rsqrtf(var + EPS);
    float a = prelu_a[0];
    float acc1 = 0.f, acc2 = 0.f, acc3 = 0.f;
    #pragma unroll
    for (int k = lane; k < DK; k += 32) {
        float z = (c * g_P0[k] + d * g_P1[k]) * rstd;
        float tv = z * ln_g[k] + ln_b[k];
        tv = tv >= 0.f ? tv : a * tv;
        acc1 += tv * g_M1[k];
        acc2 += tv * g_M2[k];
        acc3 += tv * g_M3[k];
    }
    acc1 = warpSum(acc1); acc2 = warpSum(acc2); acc3 = warpSum(acc3);
    if (lane == 0) {
        out[warp]  = acc1 + g_cst[7];  // nodes_scores + all constant biases
        g_sB[warp] = acc2 + g_cst[8];
        g_sF[warp] = acc3 + g_cst[9];
    }
}

// ---------------- K_edge: cosine weight * scalar payload, scatter-add (warp per edge) ----------------
template<int D4>
__global__ void edge_kernel(const float* __restrict__ vis, const int* __restrict__ ei,
                            const float* __restrict__ rn, const float* __restrict__ s,
                            float* __restrict__ out) {
    int warp = (blockIdx.x * blockDim.x + threadIdx.x) >> 5;
    int lane = threadIdx.x & 31;
    if (warp >= NE) return;
    int src = ei[warp];
    int dst = ei[NE + warp];
    const float4* a = reinterpret_cast<const float4*>(vis) + (size_t)src * D4;
    const float4* b = reinterpret_cast<const float4*>(vis) + (size_t)dst * D4;
    float acc = 0.f;
    #pragma unroll 4
    for (int k = lane; k < D4; k += 32) {
        float4 p = a[k];
        float4 q = b[k];
        acc += p.x * q.x + p.y * q.y + p.z * q.z + p.w * q.w;
    }
    acc = warpSum(acc);
    if (lane == 0) {
        float w = acc * rn[src] * rn[dst];
        atomicAdd(&out[dst], w * s[src]);
    }
}

// ---------------- launch ----------------
extern "C" void kernel_launch(void* const* d_in, const int* in_sizes, int n_in,
                              void* d_out, int out_size) {
    const float* x           = (const float*)d_in[0];
    const float* visual_body = (const float*)d_in[1];
    const float* visual_face = (const float*)d_in[2];
    const float* Wq          = (const float*)d_in[3];
    const float* Wk          = (const float*)d_in[4];
    const float* Wv          = (const float*)d_in[5];
    const float* ln_g        = (const float*)d_in[6];
    const float* ln_b        = (const float*)d_in[7];
    const float* prelu_a     = (const float*)d_in[8];
    const float* mlp_W       = (const float*)d_in[9];
    const float* mlp_b       = (const float*)d_in[10];
    const float* np_W        = (const float*)d_in[11];
    const float* np_b        = (const float*)d_in[12];
    const float* body_W      = (const float*)d_in[13];
    const float* body_b      = (const float*)d_in[14];
    const float* face_W      = (const float*)d_in[15];
    const float* face_b      = (const float*)d_in[16];
    const float* pb_W        = (const float*)d_in[17];
    const float* pb_b        = (const float*)d_in[18];
    const float* pf_W        = (const float*)d_in[19];
    const float* pf_b        = (const float*)d_in[20];
    const int*   ei_body     = (const int*)d_in[21];
    const int*   ei_face     = (const int*)d_in[22];
    float* out = (float*)d_out;

    float* d_rnB; cudaGetSymbolAddress((void**)&d_rnB, g_rnB);
    float* d_rnF; cudaGetSymbolAddress((void**)&d_rnF, g_rnF);
    float* d_sB;  cudaGetSymbolAddress((void**)&d_sB, g_sB);
    float* d_sF;  cudaGetSymbolAddress((void**)&d_sF, g_sF);

    precompute_kernel<<<1, 512>>>(Wq, Wk, Wv, mlp_W, mlp_b, np_W, np_b,
                                  body_W, body_b, face_W, face_b,
                                  pb_W, pb_b, pf_W, pf_b);

    // reciprocal norms: warp per node
    norm_kernel<VB / 4><<<(NN * 32) / 256, 256>>>(visual_body, d_rnB);
    norm_kernel<VF / 4><<<(NN * 32) / 256, 256>>>(visual_face, d_rnF);

    // attention: block per graph
    attn_kernel<<<NB, NG>>>(x);

    // node stage: warp per node
    node_kernel<<<(NN * 32) / 256, 256>>>(ln_g, ln_b, prelu_a, out);

    // edge stages: warp per edge
    edge_kernel<VB / 4><<<(NE * 32) / 256, 256>>>(visual_body, ei_body, d_rnB, d_sB, out);
    edge_kernel<VF / 4><<<(NE * 32) / 256, 256>>>(visual_face, ei_face, d_rnF, d_sF, out);
}

// round 2
// speedup vs baseline: 1.2901x; 1.2901x over previous
#include <cuda_runtime.h>
#include <cuda_fp16.h>
#include <math.h>

// Problem constants (fixed shapes)
#define NN 8192
#define NB 32
#define NG 256      // nodes per graph
#define NE 65536
#define DK 512
#define HH 32
#define VB 2048
#define VF 512
#define EPS 1e-5f

// ---------------- device scratch (no allocations allowed) ----------------
__device__ float g_c[NN], g_d[NN];             // attention-derived scalars per node
__device__ float g_sB[NN], g_sF[NN];           // per-node scalar message payloads
__device__ __half2 g_vnB[NN * VB / 2];         // normalized visual_body, fp16 (32 MB)
__device__ __half2 g_vnF[NN * VF / 2];         // normalized visual_face, fp16 (8 MB)
__device__ float g_P0[DK], g_P1[DK];           // centered Wv rows
__device__ float g_M1[DK], g_M2[DK], g_M3[DK]; // folded mlp_W projections
__device__ float g_cst[12];
// g_cst: 0..3 = g00,g01,g10,g11 ; 4..6 = s00,s01,s11 ; 7 = out_const ; 8 = bias2 ; 9 = bias3

// ---------------- helpers ----------------
__device__ __forceinline__ float blockReduceSum(float v, float* red) {
    int t = threadIdx.x;
    red[t] = v;
    __syncthreads();
    for (int s = blockDim.x >> 1; s > 0; s >>= 1) {
        if (t < s) red[t] += red[t + s];
        __syncthreads();
    }
    float r = red[0];
    __syncthreads();
    return r;
}

__device__ __forceinline__ float warpSum(float v) {
    #pragma unroll
    for (int o = 16; o; o >>= 1) v += __shfl_xor_sync(0xFFFFFFFFu, v, o);
    return v;
}

// ---------------- K0: one-block precompute of all small constants ----------------
__global__ void precompute_kernel(
    const float* __restrict__ Wq, const float* __restrict__ Wk, const float* __restrict__ Wv,
    const float* __restrict__ mlp_W, const float* __restrict__ mlp_b,
    const float* __restrict__ np_W, const float* __restrict__ np_b,
    const float* __restrict__ body_W, const float* __restrict__ body_b,
    const float* __restrict__ face_W, const float* __restrict__ face_b,
    const float* __restrict__ pb_W, const float* __restrict__ pb_b,
    const float* __restrict__ pf_W, const float* __restrict__ pf_b)
{
    __shared__ float red[512];
    __shared__ float sh_u2[HH], sh_u3[HH];
    __shared__ float sh_res[12];
    int t = threadIdx.x;   // 512 threads

    // u2 = body_W @ pb_W ; u3 = face_W @ pf_W  (each [32])
    if (t < HH) {
        float a2 = 0.f, a3 = 0.f;
        #pragma unroll
        for (int j = 0; j < HH; ++j) {
            a2 += body_W[t * HH + j] * pb_W[j];
            a3 += face_W[t * HH + j] * pf_W[j];
        }
        sh_u2[t] = a2;
        sh_u3[t] = a3;
    }
    __syncthreads();

    float wq0 = Wq[t], wq1 = Wq[DK + t];
    float wk0 = Wk[t], wk1 = Wk[DK + t];
    float wv0 = Wv[t], wv1 = Wv[DK + t];

    float g00 = blockReduceSum(wq0 * wk0, red);
    float g01 = blockReduceSum(wq0 * wk1, red);
    float g10 = blockReduceSum(wq1 * wk0, red);
    float g11 = blockReduceSum(wq1 * wk1, red);
    float sum0 = blockReduceSum(wv0, red);
    float sum1 = blockReduceSum(wv1, red);
    float sq00 = blockReduceSum(wv0 * wv0, red);
    float sq01 = blockReduceSum(wv0 * wv1, red);
    float sq11 = blockReduceSum(wv1 * wv1, red);
    float bu1 = blockReduceSum(t < HH ? mlp_b[t] * np_W[t] : 0.f, red);
    float bu2 = blockReduceSum(t < HH ? mlp_b[t] * sh_u2[t] : 0.f, red);
    float bu3 = blockReduceSum(t < HH ? mlp_b[t] * sh_u3[t] : 0.f, red);
    float bvB = blockReduceSum(t < HH ? body_b[t] * pb_W[t] : 0.f, red);
    float bvF = blockReduceSum(t < HH ? face_b[t] * pf_W[t] : 0.f, red);

    if (t == 0) {
        float m0 = sum0 / (float)DK, m1 = sum1 / (float)DK;
        sh_res[0] = g00; sh_res[1] = g01; sh_res[2] = g10; sh_res[3] = g11;
        sh_res[4] = sq00 / (float)DK - m0 * m0;   // s00
        sh_res[5] = sq01 / (float)DK - m0 * m1;   // s01
        sh_res[6] = sq11 / (float)DK - m1 * m1;   // s11
        sh_res[7] = bu1 + np_b[0] + pb_b[0] + pf_b[0]; // out_const
        sh_res[8] = bu2 + bvB;                          // bias2
        sh_res[9] = bu3 + bvF;                          // bias3
        sh_res[10] = m0;
        sh_res[11] = m1;
    }
    __syncthreads();

    if (t < 12) g_cst[t] = sh_res[t];

    float m0 = sh_res[10], m1 = sh_res[11];
    g_P0[t] = wv0 - m0;
    g_P1[t] = wv1 - m1;

    float a1 = 0.f, a2 = 0.f, a3 = 0.f;
    #pragma unroll
    for (int l = 0; l < HH; ++l) {
        float w = mlp_W[t * HH + l];
        a1 += w * np_W[l];
        a2 += w * sh_u2[l];
        a3 += w * sh_u3[l];
    }
    g_M1[t] = a1;
    g_M2[t] = a2;
    g_M3[t] = a3;
}

// ---------------- K_norm: normalize visual rows -> fp16 (warp per node) ----------------
template<int D4>
__global__ void norm_write_kernel(const float* __restrict__ vis, __half2* __restrict__ vn) {
    int warp = (blockIdx.x * blockDim.x + threadIdx.x) >> 5;
    int lane = threadIdx.x & 31;
    if (warp >= NN) return;
    const float4* v = reinterpret_cast<const float4*>(vis) + (size_t)warp * D4;
    float acc = 0.f;
    #pragma unroll 4
    for (int k = lane; k < D4; k += 32) {
        float4 p = v[k];
        acc += p.x * p.x + p.y * p.y + p.z * p.z + p.w * p.w;
    }
    acc = warpSum(acc);
    float rs = rsqrtf(acc + 1e-8f);
    __half2* o = vn + (size_t)warp * (D4 * 2);
    #pragma unroll 4
    for (int k = lane; k < D4; k += 32) {
        float4 p = v[k];   // second read: L1/L2 hit
        o[2 * k]     = __floats2half2_rn(p.x * rs, p.y * rs);
        o[2 * k + 1] = __floats2half2_rn(p.z * rs, p.w * rs);
    }
}

// ---------------- K_attn: per-graph rank-2 attention -> (c,d) per node ----------------
// 8 warps/block, warp per query row; 32 blocks per graph -> grid 1024
__global__ void attn_kernel(const float* __restrict__ x) {
    __shared__ float sa[NG], sb[NG];
    int g = blockIdx.x >> 5;          // graph
    int bi = blockIdx.x & 31;         // block-within-graph
    int t = threadIdx.x;              // 256 threads
    int node = g * NG + t;
    sa[t] = x[2 * node];
    sb[t] = x[2 * node + 1];
    __syncthreads();

    float g00 = g_cst[0], g01 = g_cst[1], g10 = g_cst[2], g11 = g_cst[3];
    const float inv = 0.04419417382415922f; // 1/sqrt(512)
    int warp = t >> 5, lane = t & 31;
    int i = bi * 8 + warp;            // query row

    float ai = sa[i], bi2 = sb[i];
    float alpha = (ai * g00 + bi2 * g10) * inv;
    float beta  = (ai * g01 + bi2 * g11) * inv;
    float m = -1e30f;
    #pragma unroll
    for (int j = lane; j < NG; j += 32)
        m = fmaxf(m, alpha * sa[j] + beta * sb[j]);
    #pragma unroll
    for (int o = 16; o; o >>= 1) m = fmaxf(m, __shfl_xor_sync(0xFFFFFFFFu, m, o));
    float s = 0.f, sA = 0.f, sBv = 0.f;
    #pragma unroll
    for (int j = lane; j < NG; j += 32) {
        float e = __expf(alpha * sa[j] + beta * sb[j] - m);
        s += e; sA += e * sa[j]; sBv += e * sb[j];
    }
    s = warpSum(s); sA = warpSum(sA); sBv = warpSum(sBv);
    if (lane == 0) {
        g_c[g * NG + i] = sA / s;
        g_d[g * NG + i] = sBv / s;
    }
}

// ---------------- K_node: LN + PReLU + folded projections (warp per node) ----------------
__global__ void node_kernel(const float* __restrict__ ln_g, const float* __restrict__ ln_b,
                            const float* __restrict__ prelu_a, float* __restrict__ out) {
    int warp = (blockIdx.x * blockDim.x + threadIdx.x) >> 5;
    int lane = threadIdx.x & 31;
    if (warp >= NN) return;
    float c = g_c[warp], d = g_d[warp];
    float s00 = g_cst[4], s01 = g_cst[5], s11 = g_cst[6];
    float var = c * c * s00 + 2.f * c * d * s01 + d * d * s11;
    float rstd = rsqrtf(var + EPS);
    float a = prelu_a[0];
    float acc1 = 0.f, acc2 = 0.f, acc3 = 0.f;
    #pragma unroll
    for (int k = lane; k < DK; k += 32) {
        float z = (c * g_P0[k] + d * g_P1[k]) * rstd;
        float tv = z * ln_g[k] + ln_b[k];
        tv = tv >= 0.f ? tv : a * tv;
        acc1 += tv * g_M1[k];
        acc2 += tv * g_M2[k];
        acc3 += tv * g_M3[k];
    }
    acc1 = warpSum(acc1); acc2 = warpSum(acc2); acc3 = warpSum(acc3);
    if (lane == 0) {
        out[warp]  = acc1 + g_cst[7];  // nodes_scores + all constant biases
        g_sB[warp] = acc2 + g_cst[8];
        g_sF[warp] = acc3 + g_cst[9];
    }
}

// ---------------- K_edge: fp16 cosine * scalar payload, scatter-add (warp per edge) ----------------
// D8 = halves-per-row / 8 (int4 granules per row)
template<int D8>
__global__ void edge_kernel(const __half2* __restrict__ vn, const int* __restrict__ ei,
                            const float* __restrict__ s, float* __restrict__ out) {
    int warp = (blockIdx.x * blockDim.x + threadIdx.x) >> 5;
    int lane = threadIdx.x & 31;
    if (warp >= NE) return;
    int src = ei[warp];
    int dst = ei[NE + warp];
    const int4* a = reinterpret_cast<const int4*>(vn) + (size_t)src * D8;
    const int4* b = reinterpret_cast<const int4*>(vn) + (size_t)dst * D8;
    float acc = 0.f;
    #pragma unroll
    for (int k = lane; k < D8; k += 32) {
        int4 pa = a[k];
        int4 pb = b[k];
        const __half2* ha = reinterpret_cast<const __half2*>(&pa);
        const __half2* hb = reinterpret_cast<const __half2*>(&pb);
        #pragma unroll
        for (int u = 0; u < 4; ++u) {
            float2 fa = __half22float2(ha[u]);
            float2 fb = __half22float2(hb[u]);
            acc += fa.x * fb.x + fa.y * fb.y;
        }
    }
    acc = warpSum(acc);
    if (lane == 0) {
        atomicAdd(&out[dst], acc * s[src]);
    }
}

// ---------------- launch ----------------
extern "C" void kernel_launch(void* const* d_in, const int* in_sizes, int n_in,
                              void* d_out, int out_size) {
    const float* x           = (const float*)d_in[0];
    const float* visual_body = (const float*)d_in[1];
    const float* visual_face = (const float*)d_in[2];
    const float* Wq          = (const float*)d_in[3];
    const float* Wk          = (const float*)d_in[4];
    const float* Wv          = (const float*)d_in[5];
    const float* ln_g        = (const float*)d_in[6];
    const float* ln_b        = (const float*)d_in[7];
    const float* prelu_a     = (const float*)d_in[8];
    const float* mlp_W       = (const float*)d_in[9];
    const float* mlp_b       = (const float*)d_in[10];
    const float* np_W        = (const float*)d_in[11];
    const float* np_b        = (const float*)d_in[12];
    const float* body_W      = (const float*)d_in[13];
    const float* body_b      = (const float*)d_in[14];
    const float* face_W      = (const float*)d_in[15];
    const float* face_b      = (const float*)d_in[16];
    const float* pb_W        = (const float*)d_in[17];
    const float* pb_b        = (const float*)d_in[18];
    const float* pf_W        = (const float*)d_in[19];
    const float* pf_b        = (const float*)d_in[20];
    const int*   ei_body     = (const int*)d_in[21];
    const int*   ei_face     = (const int*)d_in[22];
    float* out = (float*)d_out;

    __half2* d_vnB; cudaGetSymbolAddress((void**)&d_vnB, g_vnB);
    __half2* d_vnF; cudaGetSymbolAddress((void**)&d_vnF, g_vnF);
    float* d_sB;  cudaGetSymbolAddress((void**)&d_sB, g_sB);
    float* d_sF;  cudaGetSymbolAddress((void**)&d_sF, g_sF);

    precompute_kernel<<<1, 512>>>(Wq, Wk, Wv, mlp_W, mlp_b, np_W, np_b,
                                  body_W, body_b, face_W, face_b,
                                  pb_W, pb_b, pf_W, pf_b);

    // normalize visuals to fp16: warp per node
    norm_write_kernel<VB / 4><<<(NN * 32) / 256, 256>>>(visual_body, d_vnB);
    norm_write_kernel<VF / 4><<<(NN * 32) / 256, 256>>>(visual_face, d_vnF);

    // attention: 8 warps/block, 32 blocks per graph
    attn_kernel<<<NB * 32, NG>>>(x);

    // node stage: warp per node
    node_kernel<<<(NN * 32) / 256, 256>>>(ln_g, ln_b, prelu_a, out);

    // edge stages: warp per edge
    edge_kernel<VB / 8><<<(NE * 32) / 256, 256>>>(d_vnB, ei_body, d_sB, out);
    edge_kernel<VF / 8><<<(NE * 32) / 256, 256>>>(d_vnF, ei_face, d_sF, out);
}